// round 2
// baseline (speedup 1.0000x reference)
#include <cuda_runtime.h>

// Problem constants
#define NODES   32768            // B*N = 8*4096
#define NEDGE   524288
#define HDIM    128
#define RNUM    8
#define LNUM    2
#define KTOT    (HDIM + RNUM*HDIM)   // 1152

// ---------------- scratch (static device globals; no allocation) ------------
__device__ float g_x0[(size_t)NODES * HDIM];                 // 16.8 MB
__device__ float g_x1[(size_t)NODES * HDIM];                 // 16.8 MB
__device__ float g_S [(size_t)NODES * RNUM * HDIM];          // 134 MB
__device__ float g_Wc[LNUM][KTOT * HDIM];                    // 1.18 MB
__device__ float g_Wp[HDIM * HDIM];
__device__ int   g_rowptr[NODES + 1];
__device__ int   g_cursor[NODES];
__device__ float g_invdeg[NODES];
__device__ int   g_edges[NEDGE];                             // packed src | type<<16
__device__ int   g_cnt[NODES];

// ---------------- CSR build -------------------------------------------------
__global__ void zero_cnt_kernel() {
    int i = blockIdx.x * blockDim.x + threadIdx.x;
    if (i < NODES) g_cnt[i] = 0;
}

__global__ void hist_kernel(const int* __restrict__ dst) {
    int i = blockIdx.x * blockDim.x + threadIdx.x;
    if (i < NEDGE) atomicAdd(&g_cnt[dst[i]], 1);
}

// single block, 1024 threads; each owns 32 consecutive nodes
__global__ void scan_kernel() {
    __shared__ int sh[1024];
    int t = threadIdx.x;
    int base = t * 32;
    int local[32];
    int sum = 0;
#pragma unroll
    for (int i = 0; i < 32; i++) { local[i] = g_cnt[base + i]; sum += local[i]; }
    sh[t] = sum;
    __syncthreads();
    for (int off = 1; off < 1024; off <<= 1) {
        int v = (t >= off) ? sh[t - off] : 0;
        __syncthreads();
        sh[t] += v;
        __syncthreads();
    }
    int run = sh[t] - sum;   // exclusive prefix
#pragma unroll
    for (int i = 0; i < 32; i++) {
        g_rowptr[base + i] = run;
        g_cursor[base + i] = run;
        g_invdeg[base + i] = 1.0f / (float)max(local[i], 1);
        run += local[i];
    }
    if (t == 1023) g_rowptr[NODES] = run;
}

__global__ void scatter_kernel(const int* __restrict__ src,
                               const int* __restrict__ dst,
                               const int* __restrict__ et) {
    int i = blockIdx.x * blockDim.x + threadIdx.x;
    if (i < NEDGE) {
        int d = dst[i];
        int pos = atomicAdd(&g_cursor[d], 1);
        g_edges[pos] = (src[i] & 0xFFFF) | (et[i] << 16);
    }
}

// ---------------- weight prep: build W_cat (K-major: Wc[k*H+n]) -------------
__global__ void prep_w_kernel(const float* __restrict__ pW,
                              const float* __restrict__ sW,
                              const float* __restrict__ rW) {
    const int total = HDIM * HDIM + LNUM * KTOT * HDIM;
    for (int idx = blockIdx.x * blockDim.x + threadIdx.x; idx < total;
         idx += gridDim.x * blockDim.x) {
        if (idx < HDIM * HDIM) {
            int k = idx / HDIM, n = idx % HDIM;
            g_Wp[idx] = pW[n * HDIM + k];                  // proj_W[g,h] -> Wp[h,g]
        } else {
            int j  = idx - HDIM * HDIM;
            int l  = j / (KTOT * HDIM);
            int jj = j % (KTOT * HDIM);
            int k  = jj / HDIM, n = jj % HDIM;
            float v;
            if (k < HDIM) {
                v = sW[((size_t)l * HDIM + n) * HDIM + k];           // self_W[l,n,k]
            } else {
                int kk = k - HDIM;
                int r = kk >> 7, h = kk & 127;
                v = rW[(((size_t)(l * RNUM + r) * HDIM) + n) * HDIM + h]; // rel_W[l,r,n,h]
            }
            g_Wc[l][jj] = v;
        }
    }
}

// ---------------- embedding: x0 = concept_emb[cid] + kind_emb[kid] ----------
__global__ void embed_kernel(const int* __restrict__ cid,
                             const int* __restrict__ kid,
                             const float* __restrict__ ce,
                             const float* __restrict__ ke) {
    int i = blockIdx.x * blockDim.x + threadIdx.x;   // over NODES*32 float4s
    int v = i >> 5, j = i & 31;
    float4 a = ((const float4*)ce)[(size_t)cid[v] * 32 + j];
    float4 b = ((const float4*)ke)[(size_t)kid[v] * 32 + j];
    float4 o;
    o.x = a.x + b.x; o.y = a.y + b.y; o.z = a.z + b.z; o.w = a.w + b.w;
    ((float4*)g_x0)[(size_t)v * 32 + j] = o;
}

// ---------------- aggregation: one warp per dst node ------------------------
// S[v, r, :] = inv_deg[v] * sum_{edges (s->v) of type r} x[s, :]
__global__ void agg_kernel(const float* __restrict__ x) {
    int warp = (blockIdx.x * blockDim.x + threadIdx.x) >> 5;
    int lane = threadIdx.x & 31;
    int v = warp;                      // grid covers exactly NODES warps
    int s = g_rowptr[v], e = g_rowptr[v + 1];
    float4 acc[RNUM];
#pragma unroll
    for (int r = 0; r < RNUM; r++) acc[r] = make_float4(0.f, 0.f, 0.f, 0.f);
    const float4* x4 = (const float4*)x;
    for (int i = s; i < e; i++) {
        int p   = g_edges[i];
        int src = p & 0xFFFF;
        int r   = p >> 16;
        float4 xv = x4[(size_t)src * 32 + lane];
        switch (r) {   // r is warp-uniform -> cheap uniform branch
            case 0: acc[0].x += xv.x; acc[0].y += xv.y; acc[0].z += xv.z; acc[0].w += xv.w; break;
            case 1: acc[1].x += xv.x; acc[1].y += xv.y; acc[1].z += xv.z; acc[1].w += xv.w; break;
            case 2: acc[2].x += xv.x; acc[2].y += xv.y; acc[2].z += xv.z; acc[2].w += xv.w; break;
            case 3: acc[3].x += xv.x; acc[3].y += xv.y; acc[3].z += xv.z; acc[3].w += xv.w; break;
            case 4: acc[4].x += xv.x; acc[4].y += xv.y; acc[4].z += xv.z; acc[4].w += xv.w; break;
            case 5: acc[5].x += xv.x; acc[5].y += xv.y; acc[5].z += xv.z; acc[5].w += xv.w; break;
            case 6: acc[6].x += xv.x; acc[6].y += xv.y; acc[6].z += xv.z; acc[6].w += xv.w; break;
            default: acc[7].x += xv.x; acc[7].y += xv.y; acc[7].z += xv.z; acc[7].w += xv.w; break;
        }
    }
    float inv = g_invdeg[v];
    float4* S4 = (float4*)g_S;
#pragma unroll
    for (int r = 0; r < RNUM; r++) {
        float4 o;
        o.x = acc[r].x * inv; o.y = acc[r].y * inv;
        o.z = acc[r].z * inv; o.w = acc[r].w * inv;
        S4[((size_t)v * RNUM + r) * 32 + lane] = o;
    }
}

// ---------------- fused SGEMM: out = act(A_cat @ W + bias) [* mask] ---------
// A_cat: cols [0,K1) from A1 (lda=K1), cols [K1,K) from A2 (lda=K-K1)
// 128x128 block tile, BK=16, 256 threads, 8x8 per-thread micro-tile.
__global__ __launch_bounds__(256, 2)
void gemm_kernel(const float* __restrict__ A1, const float* __restrict__ A2,
                 int K1, int K, const float* __restrict__ W,
                 const float* __restrict__ bias, const int* __restrict__ mask,
                 int relu, float* __restrict__ out) {
    __shared__ float As[16 * 128];   // [kk][m]
    __shared__ float Bs[16 * 128];   // [kk][n]
    int tid = threadIdx.x;
    int m0 = blockIdx.x * 128;
    int ty = tid >> 4, tx = tid & 15;

    float acc[8][8];
#pragma unroll
    for (int i = 0; i < 8; i++)
#pragma unroll
        for (int j = 0; j < 8; j++) acc[i][j] = 0.f;

    for (int k0 = 0; k0 < K; k0 += 16) {
        const float* Ab; int lda, kc;
        if (k0 < K1) { Ab = A1; lda = K1;      kc = k0; }
        else         { Ab = A2; lda = K - K1;  kc = k0 - K1; }
#pragma unroll
        for (int i = 0; i < 2; i++) {
            int vec = tid * 2 + i;
            // A tile: 128 rows x 16 k  (512 float4s)
            int m = vec >> 2, kv = vec & 3;
            float4 a = *(const float4*)&Ab[(size_t)(m0 + m) * lda + kc + kv * 4];
            As[(kv * 4 + 0) * 128 + m] = a.x;
            As[(kv * 4 + 1) * 128 + m] = a.y;
            As[(kv * 4 + 2) * 128 + m] = a.z;
            As[(kv * 4 + 3) * 128 + m] = a.w;
            // B tile: 16 k x 128 n (512 float4s)
            int kk = vec >> 5, nv = vec & 31;
            *(float4*)&Bs[kk * 128 + nv * 4] =
                *(const float4*)&W[(size_t)(k0 + kk) * 128 + nv * 4];
        }
        __syncthreads();
#pragma unroll
        for (int kk = 0; kk < 16; kk++) {
            float4 a0 = *(const float4*)&As[kk * 128 + ty * 8];
            float4 a1 = *(const float4*)&As[kk * 128 + ty * 8 + 4];
            float4 b0 = *(const float4*)&Bs[kk * 128 + tx * 8];
            float4 b1 = *(const float4*)&Bs[kk * 128 + tx * 8 + 4];
            float av[8] = {a0.x, a0.y, a0.z, a0.w, a1.x, a1.y, a1.z, a1.w};
            float bv[8] = {b0.x, b0.y, b0.z, b0.w, b1.x, b1.y, b1.z, b1.w};
#pragma unroll
            for (int i = 0; i < 8; i++)
#pragma unroll
                for (int j = 0; j < 8; j++) acc[i][j] += av[i] * bv[j];
        }
        __syncthreads();
    }

    // epilogue: + bias, optional relu, optional mask, vectorized store
#pragma unroll
    for (int i = 0; i < 8; i++) {
        int m = m0 + ty * 8 + i;
        float mk = 1.0f;
        if (mask) mk = mask[m] ? 1.0f : 0.0f;
#pragma unroll
        for (int jb = 0; jb < 2; jb++) {
            int n = tx * 8 + jb * 4;
            float4 o;
            float v0 = acc[i][jb * 4 + 0] + bias[n + 0];
            float v1 = acc[i][jb * 4 + 1] + bias[n + 1];
            float v2 = acc[i][jb * 4 + 2] + bias[n + 2];
            float v3 = acc[i][jb * 4 + 3] + bias[n + 3];
            if (relu) {
                v0 = fmaxf(v0, 0.f); v1 = fmaxf(v1, 0.f);
                v2 = fmaxf(v2, 0.f); v3 = fmaxf(v3, 0.f);
            }
            o.x = v0 * mk; o.y = v1 * mk; o.z = v2 * mk; o.w = v3 * mk;
            *(float4*)&out[(size_t)m * 128 + n] = o;
        }
    }
}

// ---------------- launch ----------------------------------------------------
extern "C" void kernel_launch(void* const* d_in, const int* in_sizes, int n_in,
                              void* d_out, int out_size) {
    const int*   cid  = (const int*)  d_in[0];   // [B,N]
    const int*   kid  = (const int*)  d_in[1];   // [B,N]
    const int*   mask = (const int*)  d_in[2];   // [B,N]
    const int*   eidx = (const int*)  d_in[3];   // [2,E]
    const int*   et   = (const int*)  d_in[4];   // [E]
    const float* ce   = (const float*)d_in[5];   // [VOCAB,H]
    const float* ke   = (const float*)d_in[6];   // [KINDS,H]
    const float* pW   = (const float*)d_in[7];   // [H,H]
    const float* pb   = (const float*)d_in[8];   // [H]
    const float* sW   = (const float*)d_in[9];   // [L,H,H]
    const float* sb   = (const float*)d_in[10];  // [L,H]
    const float* rW   = (const float*)d_in[11];  // [L,R,H,H]
    float* out = (float*)d_out;

    const int* esrc = eidx;
    const int* edst = eidx + NEDGE;

    // symbol addresses for buffer args (host-side API, not stream work)
    float *x0p, *x1p, *Sp, *Wcp, *Wpp;
    cudaGetSymbolAddress((void**)&x0p, g_x0);
    cudaGetSymbolAddress((void**)&x1p, g_x1);
    cudaGetSymbolAddress((void**)&Sp,  g_S);
    cudaGetSymbolAddress((void**)&Wcp, (const void*)g_Wc);
    cudaGetSymbolAddress((void**)&Wpp, g_Wp);

    // 1) CSR build
    zero_cnt_kernel<<<NODES / 256, 256>>>();
    hist_kernel<<<NEDGE / 256, 256>>>(edst);
    scan_kernel<<<1, 1024>>>();
    scatter_kernel<<<NEDGE / 256, 256>>>(esrc, edst, et);

    // 2) weights + embedding
    prep_w_kernel<<<304, 256>>>(pW, sW, rW);
    embed_kernel<<<(NODES * 32) / 256, 256>>>(cid, kid, ce, ke);

    // 3) projection: x1 = x0 @ Wp + pb     (K=128, single source, no relu)
    gemm_kernel<<<NODES / 128, 256>>>(x0p, x0p, HDIM, HDIM, Wpp, pb,
                                      nullptr, 0, x1p);

    // 4) layer 0
    agg_kernel<<<NODES / 8, 256>>>(x1p);
    gemm_kernel<<<NODES / 128, 256>>>(x1p, Sp, HDIM, KTOT, Wcp, sb,
                                      nullptr, 1, x0p);

    // 5) layer 1 (write directly to output with mask)
    agg_kernel<<<NODES / 8, 256>>>(x0p);
    gemm_kernel<<<NODES / 128, 256>>>(x0p, Sp, HDIM, KTOT, Wcp + KTOT * HDIM,
                                      sb + HDIM, mask, 1, out);
}

// round 4
// speedup vs baseline: 1.9613x; 1.9613x over previous
#include <cuda_runtime.h>
#include <cstdint>

// Problem constants
#define NODES   32768            // B*N = 8*4096
#define NEDGE   524288
#define HDIM    128
#define RNUM    8
#define LNUM    2
#define KTOT    (HDIM + RNUM*HDIM)   // 1152
#define CHUNK   32                   // K per pipeline stage
#define PADK    36                   // smem row stride in floats (bank-conflict-free)
#define TILEF   (128 * PADK)         // floats per tile buffer
#define GEMM_SMEM (4 * TILEF * 4)    // 2 bufs x (A+B) = 73728 bytes

// ---------------- scratch (static device globals; no allocation) ------------
__device__ float g_x0[(size_t)NODES * HDIM];
__device__ float g_x1[(size_t)NODES * HDIM];
__device__ float g_S [(size_t)NODES * RNUM * HDIM];
__device__ float g_Wc[LNUM][(size_t)HDIM * KTOT];            // [l][n*KTOT + k]
__device__ int   g_rowptr[NODES + 1];
__device__ int   g_cursor[NODES];
__device__ float g_invdeg[NODES];
__device__ int   g_edges[NEDGE];                             // packed src | type<<16
__device__ int   g_cnt[NODES];

__device__ __forceinline__ uint32_t f2tf32(float v) {
    uint32_t r; asm("cvt.rna.tf32.f32 %0, %1;" : "=r"(r) : "f"(v)); return r;
}
__device__ __forceinline__ void mma_tf32(float* d, const uint32_t* a,
                                         uint32_t b0, uint32_t b1) {
    asm volatile(
        "mma.sync.aligned.m16n8k8.row.col.f32.tf32.tf32.f32 "
        "{%0,%1,%2,%3}, {%4,%5,%6,%7}, {%8,%9}, {%0,%1,%2,%3};"
        : "+f"(d[0]), "+f"(d[1]), "+f"(d[2]), "+f"(d[3])
        : "r"(a[0]), "r"(a[1]), "r"(a[2]), "r"(a[3]), "r"(b0), "r"(b1));
}

// ---------------- CSR build -------------------------------------------------
__global__ void zero_cnt_kernel() {
    int i = blockIdx.x * blockDim.x + threadIdx.x;
    if (i < NODES) g_cnt[i] = 0;
}
__global__ void hist_kernel(const int* __restrict__ dst) {
    int i = blockIdx.x * blockDim.x + threadIdx.x;
    if (i < NEDGE) atomicAdd(&g_cnt[dst[i]], 1);
}
__global__ void scan_kernel() {
    __shared__ int sh[1024];
    int t = threadIdx.x;
    int base = t * 32;
    int local[32];
    int sum = 0;
#pragma unroll
    for (int i = 0; i < 32; i++) { local[i] = g_cnt[base + i]; sum += local[i]; }
    sh[t] = sum;
    __syncthreads();
    for (int off = 1; off < 1024; off <<= 1) {
        int v = (t >= off) ? sh[t - off] : 0;
        __syncthreads();
        sh[t] += v;
        __syncthreads();
    }
    int run = sh[t] - sum;
#pragma unroll
    for (int i = 0; i < 32; i++) {
        g_rowptr[base + i] = run;
        g_cursor[base + i] = run;
        g_invdeg[base + i] = 1.0f / (float)max(local[i], 1);
        run += local[i];
    }
    if (t == 1023) g_rowptr[NODES] = run;
}
__global__ void scatter_kernel(const int* __restrict__ src,
                               const int* __restrict__ dst,
                               const int* __restrict__ et) {
    int i = blockIdx.x * blockDim.x + threadIdx.x;
    if (i < NEDGE) {
        int d = dst[i];
        int pos = atomicAdd(&g_cursor[d], 1);
        g_edges[pos] = (src[i] & 0xFFFF) | (et[i] << 16);
    }
}

// ------- weight prep: Wc[l][n*KTOT + k] = [self_W[l,n,:] | rel_W[l,r,n,:]] ---
__global__ void prep_w_kernel(const float* __restrict__ sW,
                              const float* __restrict__ rW) {
    const int total = LNUM * HDIM * KTOT;
    for (int idx = blockIdx.x * blockDim.x + threadIdx.x; idx < total;
         idx += gridDim.x * blockDim.x) {
        int l  = idx / (HDIM * KTOT);
        int jj = idx % (HDIM * KTOT);
        int n  = jj / KTOT, k = jj % KTOT;
        float v;
        if (k < HDIM) {
            v = sW[((size_t)l * HDIM + n) * HDIM + k];
        } else {
            int kk = k - HDIM;
            int r = kk >> 7, h = kk & 127;
            v = rW[(((size_t)(l * RNUM + r) * HDIM) + n) * HDIM + h];
        }
        g_Wc[l][jj] = v;
    }
}

// ---------------- embedding -------------------------------------------------
__global__ void embed_kernel(const int* __restrict__ cid,
                             const int* __restrict__ kid,
                             const float* __restrict__ ce,
                             const float* __restrict__ ke) {
    int i = blockIdx.x * blockDim.x + threadIdx.x;
    int v = i >> 5, j = i & 31;
    float4 a = ((const float4*)ce)[(size_t)cid[v] * 32 + j];
    float4 b = ((const float4*)ke)[(size_t)kid[v] * 32 + j];
    float4 o;
    o.x = a.x + b.x; o.y = a.y + b.y; o.z = a.z + b.z; o.w = a.w + b.w;
    ((float4*)g_x0)[(size_t)v * 32 + j] = o;
}

// ---------------- aggregation: one warp per dst node ------------------------
__global__ void agg_kernel(const float* __restrict__ x) {
    int warp = (blockIdx.x * blockDim.x + threadIdx.x) >> 5;
    int lane = threadIdx.x & 31;
    int v = warp;
    int s = g_rowptr[v], e = g_rowptr[v + 1];
    float4 acc[RNUM];
#pragma unroll
    for (int r = 0; r < RNUM; r++) acc[r] = make_float4(0.f, 0.f, 0.f, 0.f);
    const float4* x4 = (const float4*)x;
    for (int i = s; i < e; i++) {
        int p   = g_edges[i];
        int src = p & 0xFFFF;
        int r   = p >> 16;
        float4 xv = x4[(size_t)src * 32 + lane];
        switch (r) {
            case 0: acc[0].x += xv.x; acc[0].y += xv.y; acc[0].z += xv.z; acc[0].w += xv.w; break;
            case 1: acc[1].x += xv.x; acc[1].y += xv.y; acc[1].z += xv.z; acc[1].w += xv.w; break;
            case 2: acc[2].x += xv.x; acc[2].y += xv.y; acc[2].z += xv.z; acc[2].w += xv.w; break;
            case 3: acc[3].x += xv.x; acc[3].y += xv.y; acc[3].z += xv.z; acc[3].w += xv.w; break;
            case 4: acc[4].x += xv.x; acc[4].y += xv.y; acc[4].z += xv.z; acc[4].w += xv.w; break;
            case 5: acc[5].x += xv.x; acc[5].y += xv.y; acc[5].z += xv.z; acc[5].w += xv.w; break;
            case 6: acc[6].x += xv.x; acc[6].y += xv.y; acc[6].z += xv.z; acc[6].w += xv.w; break;
            default: acc[7].x += xv.x; acc[7].y += xv.y; acc[7].z += xv.z; acc[7].w += xv.w; break;
        }
    }
    float inv = g_invdeg[v];
    float4* S4 = (float4*)g_S;
#pragma unroll
    for (int r = 0; r < RNUM; r++) {
        float4 o;
        o.x = acc[r].x * inv; o.y = acc[r].y * inv;
        o.z = acc[r].z * inv; o.w = acc[r].w * inv;
        S4[((size_t)v * RNUM + r) * 32 + lane] = o;
    }
}

// ====== tf32 mma.sync GEMM: out = act(A_cat @ B^T + bias) [* mask] ==========
// A_cat rows: cols [0,K1) from A1 (lda=K1), [K1,K) from A2 (lda=K-K1).
// B: [128 n][K k] K-major. Block tile M=128 x N=128; 8 warps in 4x2 layout,
// each warp 32(M) x 64(N). K-chunks of 32, double-buffered SMEM (pad 36).
__global__ __launch_bounds__(256, 2)
void mma_gemm_kernel(const float* __restrict__ A1, const float* __restrict__ A2,
                     int K1, int K, const float* __restrict__ Bw,
                     const float* __restrict__ bias, const int* __restrict__ mask,
                     int relu, float* __restrict__ out) {
    extern __shared__ float sm[];
    float* Abuf = sm;                 // [2][TILEF]
    float* Bbuf = sm + 2 * TILEF;     // [2][TILEF]

    int tid = threadIdx.x, wid = tid >> 5, lane = tid & 31;
    int m0 = blockIdx.x * 128;
    int wr = wid & 3, wc = wid >> 2;      // warp tile: rows wr*32, cols wc*64
    int g = lane >> 2, tg = lane & 3;

    float acc[2][8][4];
#pragma unroll
    for (int mt = 0; mt < 2; mt++)
#pragma unroll
        for (int nt = 0; nt < 8; nt++)
#pragma unroll
            for (int r = 0; r < 4; r++) acc[mt][nt][r] = 0.f;

    // staging indices: 4 float4 each for A and B per thread per chunk
    // idx = i*256 + tid ; m = idx>>3 (row), k4 = idx&7 (float4 within 32)
    const int NC = K / CHUNK;
    float4 ra[4], rb[4];

    auto ldglobal = [&](int c) {
        int kbase = c * CHUNK;
        const float* Aq; int lda, kb;
        if (kbase < K1) { Aq = A1; lda = K1;     kb = kbase; }
        else            { Aq = A2; lda = K - K1; kb = kbase - K1; }
#pragma unroll
        for (int i = 0; i < 4; i++) {
            int idx = i * 256 + tid;
            int m = idx >> 3, k4 = idx & 7;
            ra[i] = *(const float4*)&Aq[(size_t)(m0 + m) * lda + kb + k4 * 4];
            rb[i] = *(const float4*)&Bw[(size_t)m * K + kbase + k4 * 4];
        }
    };
    auto stsmem = [&](int b) {
        float* Ad = Abuf + b * TILEF;
        float* Bd = Bbuf + b * TILEF;
#pragma unroll
        for (int i = 0; i < 4; i++) {
            int idx = i * 256 + tid;
            int m = idx >> 3, k4 = idx & 7;
            float4 a, w;
            a.x = __uint_as_float(f2tf32(ra[i].x));
            a.y = __uint_as_float(f2tf32(ra[i].y));
            a.z = __uint_as_float(f2tf32(ra[i].z));
            a.w = __uint_as_float(f2tf32(ra[i].w));
            w.x = __uint_as_float(f2tf32(rb[i].x));
            w.y = __uint_as_float(f2tf32(rb[i].y));
            w.z = __uint_as_float(f2tf32(rb[i].z));
            w.w = __uint_as_float(f2tf32(rb[i].w));
            *(float4*)&Ad[m * PADK + k4 * 4] = a;
            *(float4*)&Bd[m * PADK + k4 * 4] = w;
        }
    };
    auto compute = [&](int b) {
        const float* A = Abuf + b * TILEF;
        const float* Bs = Bbuf + b * TILEF;
#pragma unroll
        for (int ks = 0; ks < 4; ks++) {
            uint32_t a[2][4];
#pragma unroll
            for (int mt = 0; mt < 2; mt++) {
                const float* ap = A + (wr * 32 + mt * 16 + g) * PADK + ks * 8 + tg;
                a[mt][0] = __float_as_uint(ap[0]);
                a[mt][1] = __float_as_uint(ap[8 * PADK]);
                a[mt][2] = __float_as_uint(ap[4]);
                a[mt][3] = __float_as_uint(ap[8 * PADK + 4]);
            }
#pragma unroll
            for (int nt = 0; nt < 8; nt++) {
                const float* bp = Bs + (wc * 64 + nt * 8 + g) * PADK + ks * 8 + tg;
                uint32_t b0 = __float_as_uint(bp[0]);
                uint32_t b1 = __float_as_uint(bp[4]);
                mma_tf32(acc[0][nt], a[0], b0, b1);
                mma_tf32(acc[1][nt], a[1], b0, b1);
            }
        }
    };

    ldglobal(0);
    stsmem(0);
    __syncthreads();
    for (int c = 0; c < NC; c++) {
        int b = c & 1;
        if (c + 1 < NC) ldglobal(c + 1);   // prefetch next chunk into regs
        compute(b);
        if (c + 1 < NC) stsmem(b ^ 1);
        __syncthreads();
    }

    // epilogue: + bias, optional relu, optional mask
#pragma unroll
    for (int mt = 0; mt < 2; mt++) {
        int rb0 = m0 + wr * 32 + mt * 16 + g;   // rows rb0 and rb0+8
        float mk0 = 1.0f, mk1 = 1.0f;
        if (mask) {
            mk0 = mask[rb0] ? 1.0f : 0.0f;
            mk1 = mask[rb0 + 8] ? 1.0f : 0.0f;
        }
#pragma unroll
        for (int nt = 0; nt < 8; nt++) {
            int n = wc * 64 + nt * 8 + tg * 2;
            float b0 = bias[n], b1 = bias[n + 1];
            float v00 = acc[mt][nt][0] + b0, v01 = acc[mt][nt][1] + b1;
            float v10 = acc[mt][nt][2] + b0, v11 = acc[mt][nt][3] + b1;
            if (relu) {
                v00 = fmaxf(v00, 0.f); v01 = fmaxf(v01, 0.f);
                v10 = fmaxf(v10, 0.f); v11 = fmaxf(v11, 0.f);
            }
            float2 o0 = make_float2(v00 * mk0, v01 * mk0);
            float2 o1 = make_float2(v10 * mk1, v11 * mk1);
            *(float2*)&out[(size_t)rb0 * 128 + n] = o0;
            *(float2*)&out[(size_t)(rb0 + 8) * 128 + n] = o1;
        }
    }
}

// ---------------- launch ----------------------------------------------------
extern "C" void kernel_launch(void* const* d_in, const int* in_sizes, int n_in,
                              void* d_out, int out_size) {
    const int*   cid  = (const int*)  d_in[0];
    const int*   kid  = (const int*)  d_in[1];
    const int*   mask = (const int*)  d_in[2];
    const int*   eidx = (const int*)  d_in[3];
    const int*   et   = (const int*)  d_in[4];
    const float* ce   = (const float*)d_in[5];
    const float* ke   = (const float*)d_in[6];
    const float* pW   = (const float*)d_in[7];
    const float* pb   = (const float*)d_in[8];
    const float* sW   = (const float*)d_in[9];
    const float* sb   = (const float*)d_in[10];
    const float* rW   = (const float*)d_in[11];
    float* out = (float*)d_out;

    const int* esrc = eidx;
    const int* edst = eidx + NEDGE;

    float *x0p, *x1p, *Sp, *Wcp;
    cudaGetSymbolAddress((void**)&x0p, g_x0);
    cudaGetSymbolAddress((void**)&x1p, g_x1);
    cudaGetSymbolAddress((void**)&Sp,  g_S);
    cudaGetSymbolAddress((void**)&Wcp, (const void*)g_Wc);

    static int smem_set = 0;
    if (!smem_set) {
        cudaFuncSetAttribute(mma_gemm_kernel,
                             cudaFuncAttributeMaxDynamicSharedMemorySize, GEMM_SMEM);
        smem_set = 1;
    }

    // 1) CSR build
    zero_cnt_kernel<<<NODES / 256, 256>>>();
    hist_kernel<<<NEDGE / 256, 256>>>(edst);
    scan_kernel<<<1, 1024>>>();
    scatter_kernel<<<NEDGE / 256, 256>>>(esrc, edst, et);

    // 2) weights + embedding
    prep_w_kernel<<<1152, 256>>>(sW, rW);
    embed_kernel<<<(NODES * 32) / 256, 256>>>(cid, kid, ce, ke);

    // 3) projection: x1 = x0 @ proj_W^T + pb   (B = proj_W [g][h], K=128)
    mma_gemm_kernel<<<NODES / 128, 256, GEMM_SMEM>>>(
        x0p, x0p, HDIM, HDIM, pW, pb, nullptr, 0, x1p);

    // 4) layer 0
    agg_kernel<<<NODES / 8, 256>>>(x1p);
    mma_gemm_kernel<<<NODES / 128, 256, GEMM_SMEM>>>(
        x1p, Sp, HDIM, KTOT, Wcp, sb, nullptr, 1, x0p);

    // 5) layer 1 (direct to output with mask)
    agg_kernel<<<NODES / 8, 256>>>(x0p);
    mma_gemm_kernel<<<NODES / 128, 256, GEMM_SMEM>>>(
        x0p, Sp, HDIM, KTOT, Wcp + (size_t)HDIM * KTOT, sb + HDIM, mask, 1, out);
}